// round 5
// baseline (speedup 1.0000x reference)
#include <cuda_runtime.h>
#include <cstdint>

// Problem constants
#define DIMM  1024
#define HEADS 16
#define HDIM  64
#define BATCH 16
#define SEQ   512

// ---------------- scratch (device globals; no cudaMalloc allowed) ----------
__device__ float g_Q[(size_t)BATCH*HEADS*SEQ*HDIM];   // [b,h,s,d]  32 MB (tf32-rounded)
__device__ float g_K[(size_t)BATCH*HEADS*SEQ*HDIM];   // 32 MB (tf32-rounded)
__device__ float g_V[(size_t)BATCH*HEADS*SEQ*HDIM];   // 32 MB (tf32-rounded)
__device__ float g_O[(size_t)BATCH*SEQ*DIMM];         // 32 MB (tf32-rounded)
__device__ float g_X [(size_t)BATCH*SEQ*DIMM];        // 32 MB x   (tf32-rounded)
__device__ float g_CT[(size_t)BATCH*SEQ*DIMM];        // 32 MB ctx (tf32-rounded)
__device__ float g_Wq[DIMM*DIMM];                      // 4 MB each (tf32-rounded)
__device__ float g_Wk[DIMM*DIMM];
__device__ float g_Wv[DIMM*DIMM];
__device__ float g_Wo[DIMM*DIMM];

// ---------------- helpers ---------------------------------------------------
__device__ __forceinline__ float to_tf32(float x) {
    uint32_t u;
    asm("cvt.rna.tf32.f32 %0, %1;" : "=r"(u) : "f"(x));
    return __uint_as_float(u);
}

__device__ __forceinline__ void mma8(float* c,
                                     uint32_t a0, uint32_t a1, uint32_t a2, uint32_t a3,
                                     uint32_t b0, uint32_t b1) {
    asm volatile(
        "mma.sync.aligned.m16n8k8.row.col.f32.tf32.tf32.f32 "
        "{%0,%1,%2,%3},{%4,%5,%6,%7},{%8,%9},{%0,%1,%2,%3};"
        : "+f"(c[0]), "+f"(c[1]), "+f"(c[2]), "+f"(c[3])
        : "r"(a0), "r"(a1), "r"(a2), "r"(a3), "r"(b0), "r"(b1));
}

__device__ __forceinline__ void cp_async16(uint32_t s, const void* g) {
    asm volatile("cp.async.cg.shared.global [%0], [%1], 16;" :: "r"(s), "l"(g));
}

// RoPE (tiled tables, adjacent-pair rotation), applied to fp32 accumulators.
__device__ __forceinline__ void rope_pair(float& e, float& o, int t, int d /*even*/) {
    const float LOG2_10000_OVER_32 = 0.41524101186092028f;
    int   i0  = d & 31;
    float fr0 = exp2f(-(float)i0       * LOG2_10000_OVER_32);
    float fr1 = exp2f(-(float)(i0 + 1) * LOG2_10000_OVER_32);
    float tf  = (float)t;
    float s0, c0, s1, c1;
    sincosf(tf * fr0, &s0, &c0);
    sincosf(tf * fr1, &s1, &c1);
    float ne = e * c0 - o * s0;
    float no = o * c1 + e * s1;
    e = ne; o = no;
}

// ---------------- tf32 pre-truncation pass -----------------------------------
__global__ void __launch_bounds__(256) trunc_k(const float* __restrict__ s,
                                               float* __restrict__ d, int n4) {
    int i = blockIdx.x * 256 + threadIdx.x;
    if (i < n4) {
        float4 v = reinterpret_cast<const float4*>(s)[i];
        v.x = to_tf32(v.x); v.y = to_tf32(v.y);
        v.z = to_tf32(v.z); v.w = to_tf32(v.w);
        reinterpret_cast<float4*>(d)[i] = v;
    }
}

// ---------------- pipelined GEMM: 128x128 tile, 4 warps (64x64 each) --------
// All operands pre-truncated to tf32 -> NO cvt in the inner loop.
// MODE: 0 = Q proj (+RoPE), 1 = K proj (+RoPE), 2 = V proj, 5 = out = O@Wo+bo
template <int MODE>
__global__ void __launch_bounds__(128) gemm3_k(const float* __restrict__ Ain,
                                               const float* __restrict__ Bin,
                                               float*       __restrict__ Cout,
                                               const float* __restrict__ bias) {
    const int tid  = threadIdx.x;
    const int lane = tid & 31;
    const int warp = tid >> 5;
    const int wm   = warp >> 1;        // 0..1 (64 rows)
    const int wn   = warp & 1;         // 0..1 (64 cols)
    const int mBase = blockIdx.y * 128;
    const int nBase = blockIdx.x * 128;

    const float* A = (MODE == 5) ? g_O : Ain;
    const float* B = Bin;

    __shared__ float As[2][128 * 20];  // stride 20: conflict-free
    __shared__ float Bs[2][16 * 136];  // stride 136 == 8 mod 32

    auto load_tiles = [&](int k0, int buf) {
        #pragma unroll
        for (int j = 0; j < 4; j++) {
            int idx = tid + j * 128;
            int r = idx >> 2, c4 = (idx & 3) * 4;
            cp_async16((uint32_t)__cvta_generic_to_shared(&As[buf][r * 20 + c4]),
                       A + (size_t)(mBase + r) * 1024 + k0 + c4);
        }
        #pragma unroll
        for (int j = 0; j < 4; j++) {
            int idx = tid + j * 128;
            int r = idx >> 5, c4 = (idx & 31) * 4;
            cp_async16((uint32_t)__cvta_generic_to_shared(&Bs[buf][r * 136 + c4]),
                       B + (size_t)(k0 + r) * 1024 + nBase + c4);
        }
        asm volatile("cp.async.commit_group;");
    };

    float acc[4][8][4];
    #pragma unroll
    for (int i = 0; i < 4; i++)
        #pragma unroll
        for (int j = 0; j < 8; j++)
            #pragma unroll
            for (int k = 0; k < 4; k++) acc[i][j][k] = 0.f;

    load_tiles(0, 0);
    asm volatile("cp.async.wait_group 0;");
    __syncthreads();

    for (int k0 = 0; k0 < 1024; k0 += 16) {
        const int buf = (k0 >> 4) & 1;
        if (k0 + 16 < 1024) load_tiles(k0 + 16, buf ^ 1);

        const float* Ab = As[buf];
        const float* Bb = Bs[buf];
        #pragma unroll
        for (int kk = 0; kk < 16; kk += 8) {
            const int cc = kk + (lane & 3);
            uint32_t af[4][4];
            #pragma unroll
            for (int mt = 0; mt < 4; mt++) {
                int r0 = (wm * 64 + mt * 16 + (lane >> 2)) * 20;
                af[mt][0] = __float_as_uint(Ab[r0 + cc]);
                af[mt][1] = __float_as_uint(Ab[r0 + 160 + cc]);   // +8 rows
                af[mt][2] = __float_as_uint(Ab[r0 + cc + 4]);
                af[mt][3] = __float_as_uint(Ab[r0 + 160 + cc + 4]);
            }
            uint32_t bf[8][2];
            #pragma unroll
            for (int nt = 0; nt < 8; nt++) {
                int nb = wn * 64 + nt * 8 + (lane >> 2);
                bf[nt][0] = __float_as_uint(Bb[cc * 136 + nb]);
                bf[nt][1] = __float_as_uint(Bb[(cc + 4) * 136 + nb]);
            }
            #pragma unroll
            for (int mt = 0; mt < 4; mt++)
                #pragma unroll
                for (int nt = 0; nt < 8; nt++)
                    mma8(acc[mt][nt], af[mt][0], af[mt][1], af[mt][2], af[mt][3],
                         bf[nt][0], bf[nt][1]);
        }
        asm volatile("cp.async.wait_group 0;");
        __syncthreads();
    }

    // --- epilogue ---
    #pragma unroll
    for (int mt = 0; mt < 4; mt++) {
        #pragma unroll
        for (int nt = 0; nt < 8; nt++) {
            int row = mBase + wm * 64 + mt * 16 + (lane >> 2);
            int col = nBase + wn * 64 + nt * 8 + 2 * (lane & 3);
            #pragma unroll
            for (int half = 0; half < 2; half++) {
                int   rr = row + half * 8;
                float e  = acc[mt][nt][half * 2 + 0];
                float o  = acc[mt][nt][half * 2 + 1];
                if constexpr (MODE <= 1) rope_pair(e, o, rr & (SEQ - 1), col & (HDIM - 1));
                if constexpr (MODE <= 2) {
                    int b = rr >> 9, s = rr & (SEQ - 1);
                    int h = col >> 6, d = col & (HDIM - 1);
                    float* out = (MODE == 0) ? g_Q : ((MODE == 1) ? g_K : g_V);
                    size_t off = (((size_t)(b * HEADS + h)) * SEQ + s) * HDIM + d;
                    *reinterpret_cast<float2*>(out + off) =
                        make_float2(to_tf32(e), to_tf32(o));   // pre-truncate for flash
                } else {
                    size_t off = (size_t)rr * DIMM + col;
                    *reinterpret_cast<float2*>(Cout + off) =
                        make_float2(e + bias[col], o + bias[col + 1]);  // final: full fp32
                }
            }
        }
    }
}

// ---------------- fused flash attention (scores + softmax + PV) -------------
// One CTA per (z = b*H+h, 64-row q tile). 4 warps, each owns 16 q rows.
// Q/K/V already tf32-rounded -> no cvt at load; K/V tiles via cp.async.
__global__ void __launch_bounds__(128) flash_k() {
    const int z     = blockIdx.y;
    const int qBase = blockIdx.x * 64;
    const int lane  = threadIdx.x & 31;
    const int warp  = threadIdx.x >> 5;

    const float* Qp = g_Q + (size_t)z * SEQ * HDIM;
    const float* Kp = g_K + (size_t)z * SEQ * HDIM;
    const float* Vp = g_V + (size_t)z * SEQ * HDIM;

    __shared__ float KPs[64 * 68];   // K tile, reused as P tile after QK^T
    __shared__ float Vs [64 * 68];

    uint32_t qa[8][4];
    {
        const int r0 = qBase + warp * 16 + (lane >> 2);
        #pragma unroll
        for (int kk = 0; kk < 8; kk++) {
            int c = kk * 8 + (lane & 3);
            qa[kk][0] = __float_as_uint(Qp[(size_t)r0       * HDIM + c]);
            qa[kk][1] = __float_as_uint(Qp[(size_t)(r0 + 8) * HDIM + c]);
            qa[kk][2] = __float_as_uint(Qp[(size_t)r0       * HDIM + c + 4]);
            qa[kk][3] = __float_as_uint(Qp[(size_t)(r0 + 8) * HDIM + c + 4]);
        }
    }

    float m0 = -1e30f, m1 = -1e30f, l0 = 0.f, l1 = 0.f;
    float o[8][4];
    #pragma unroll
    for (int nt = 0; nt < 8; nt++)
        #pragma unroll
        for (int i = 0; i < 4; i++) o[nt][i] = 0.f;

    for (int kt = 0; kt < 8; kt++) {
        __syncthreads();   // previous iteration's readers done with KPs/Vs
        const float* Kt = Kp + (size_t)kt * 64 * HDIM;
        const float* Vt = Vp + (size_t)kt * 64 * HDIM;
        #pragma unroll
        for (int i = 0; i < 8; i++) {
            int idx = threadIdx.x + i * 128;
            int rr = idx >> 4, cc = (idx & 15) * 4;
            cp_async16((uint32_t)__cvta_generic_to_shared(&KPs[rr * 68 + cc]),
                       Kt + rr * HDIM + cc);
            cp_async16((uint32_t)__cvta_generic_to_shared(&Vs[rr * 68 + cc]),
                       Vt + rr * HDIM + cc);
        }
        asm volatile("cp.async.commit_group;");
        asm volatile("cp.async.wait_group 0;");
        __syncthreads();

        // ---- S = Q K^T (16x64 per warp) ----
        float s[8][4];
        #pragma unroll
        for (int nt = 0; nt < 8; nt++)
            #pragma unroll
            for (int i = 0; i < 4; i++) s[nt][i] = 0.f;
        #pragma unroll
        for (int kk = 0; kk < 8; kk++) {
            const int d0 = kk * 8 + (lane & 3);
            #pragma unroll
            for (int nt = 0; nt < 8; nt++) {
                const int kvr = nt * 8 + (lane >> 2);
                uint32_t b0 = __float_as_uint(KPs[kvr * 68 + d0]);
                uint32_t b1 = __float_as_uint(KPs[kvr * 68 + d0 + 4]);
                mma8(s[nt], qa[kk][0], qa[kk][1], qa[kk][2], qa[kk][3], b0, b1);
            }
        }

        // ---- online softmax ----
        float mr0 = -1e30f, mr1 = -1e30f;
        #pragma unroll
        for (int nt = 0; nt < 8; nt++) {
            s[nt][0] *= 0.125f; s[nt][1] *= 0.125f;
            s[nt][2] *= 0.125f; s[nt][3] *= 0.125f;
            mr0 = fmaxf(mr0, fmaxf(s[nt][0], s[nt][1]));
            mr1 = fmaxf(mr1, fmaxf(s[nt][2], s[nt][3]));
        }
        mr0 = fmaxf(mr0, __shfl_xor_sync(0xffffffffu, mr0, 1));
        mr0 = fmaxf(mr0, __shfl_xor_sync(0xffffffffu, mr0, 2));
        mr1 = fmaxf(mr1, __shfl_xor_sync(0xffffffffu, mr1, 1));
        mr1 = fmaxf(mr1, __shfl_xor_sync(0xffffffffu, mr1, 2));

        float nm0 = fmaxf(m0, mr0), nm1 = fmaxf(m1, mr1);
        float f0 = __expf(m0 - nm0), f1 = __expf(m1 - nm1);
        m0 = nm0; m1 = nm1;

        float sum0 = 0.f, sum1 = 0.f;
        #pragma unroll
        for (int nt = 0; nt < 8; nt++) {
            s[nt][0] = __expf(s[nt][0] - m0);
            s[nt][1] = __expf(s[nt][1] - m0);
            s[nt][2] = __expf(s[nt][2] - m1);
            s[nt][3] = __expf(s[nt][3] - m1);
            sum0 += s[nt][0] + s[nt][1];
            sum1 += s[nt][2] + s[nt][3];
        }
        sum0 += __shfl_xor_sync(0xffffffffu, sum0, 1);
        sum0 += __shfl_xor_sync(0xffffffffu, sum0, 2);
        sum1 += __shfl_xor_sync(0xffffffffu, sum1, 1);
        sum1 += __shfl_xor_sync(0xffffffffu, sum1, 2);
        l0 = l0 * f0 + sum0;
        l1 = l1 * f1 + sum1;

        #pragma unroll
        for (int nt = 0; nt < 8; nt++) {
            o[nt][0] *= f0; o[nt][1] *= f0;
            o[nt][2] *= f1; o[nt][3] *= f1;
        }

        // ---- P -> smem (reuse K buffer), then O += P V ----
        __syncthreads();   // all warps done reading K from KPs
        {
            const int pr = warp * 16 + (lane >> 2);
            #pragma unroll
            for (int nt = 0; nt < 8; nt++) {
                int c = nt * 8 + 2 * (lane & 3);
                KPs[pr * 68 + c]           = to_tf32(s[nt][0]);
                KPs[pr * 68 + c + 1]       = to_tf32(s[nt][1]);
                KPs[(pr + 8) * 68 + c]     = to_tf32(s[nt][2]);
                KPs[(pr + 8) * 68 + c + 1] = to_tf32(s[nt][3]);
            }
        }
        __syncwarp();      // P rows are warp-private

        #pragma unroll
        for (int kk = 0; kk < 8; kk++) {
            const int pq = warp * 16 + (lane >> 2);
            const int kv = kk * 8 + (lane & 3);
            uint32_t pa0 = __float_as_uint(KPs[pq * 68 + kv]);
            uint32_t pa1 = __float_as_uint(KPs[(pq + 8) * 68 + kv]);
            uint32_t pa2 = __float_as_uint(KPs[pq * 68 + kv + 4]);
            uint32_t pa3 = __float_as_uint(KPs[(pq + 8) * 68 + kv + 4]);
            #pragma unroll
            for (int nt = 0; nt < 8; nt++) {
                const int dc = nt * 8 + (lane >> 2);
                uint32_t b0 = __float_as_uint(Vs[kv * 68 + dc]);
                uint32_t b1 = __float_as_uint(Vs[(kv + 4) * 68 + dc]);
                mma8(o[nt], pa0, pa1, pa2, pa3, b0, b1);
            }
        }
    }

    // ---- epilogue: O /= l, tf32-truncate (consumed by gemm3<5>), write ----
    const float inv0 = 1.f / l0, inv1 = 1.f / l1;
    const int b = z >> 4, h = z & 15;
    const int row = qBase + warp * 16 + (lane >> 2);
    #pragma unroll
    for (int nt = 0; nt < 8; nt++) {
        int col = h * HDIM + nt * 8 + 2 * (lane & 3);
        *reinterpret_cast<float2*>(g_O + (size_t)(b * SEQ + row) * DIMM + col)
            = make_float2(to_tf32(o[nt][0] * inv0), to_tf32(o[nt][1] * inv0));
        *reinterpret_cast<float2*>(g_O + (size_t)(b * SEQ + row + 8) * DIMM + col)
            = make_float2(to_tf32(o[nt][2] * inv1), to_tf32(o[nt][3] * inv1));
    }
}

// ---------------- launch -----------------------------------------------------
extern "C" void kernel_launch(void* const* d_in, const int* in_sizes, int n_in,
                              void* d_out, int out_size) {
    (void)in_sizes; (void)n_in; (void)out_size;
    const float* x   = (const float*)d_in[0];
    const float* ctx = (const float*)d_in[1];
    const float* Wq  = (const float*)d_in[2];
    const float* Wk  = (const float*)d_in[3];
    const float* Wv  = (const float*)d_in[4];
    const float* Wo  = (const float*)d_in[5];
    const float* bo  = (const float*)d_in[6];
    float* out = (float*)d_out;

    float *dX, *dCT, *dWq, *dWk, *dWv, *dWo;
    cudaGetSymbolAddress((void**)&dX,  g_X);
    cudaGetSymbolAddress((void**)&dCT, g_CT);
    cudaGetSymbolAddress((void**)&dWq, g_Wq);
    cudaGetSymbolAddress((void**)&dWk, g_Wk);
    cudaGetSymbolAddress((void**)&dWv, g_Wv);
    cudaGetSymbolAddress((void**)&dWo, g_Wo);

    const int nBig = BATCH * SEQ * DIMM / 4;   // 2M float4
    const int nW   = DIMM * DIMM / 4;          // 256K float4
    trunc_k<<<(nBig + 255) / 256, 256>>>(x,   dX,  nBig);
    trunc_k<<<(nBig + 255) / 256, 256>>>(ctx, dCT, nBig);
    trunc_k<<<(nW   + 255) / 256, 256>>>(Wq,  dWq, nW);
    trunc_k<<<(nW   + 255) / 256, 256>>>(Wk,  dWk, nW);
    trunc_k<<<(nW   + 255) / 256, 256>>>(Wv,  dWv, nW);
    trunc_k<<<(nW   + 255) / 256, 256>>>(Wo,  dWo, nW);

    dim3 g(8, 64), b3(128);
    gemm3_k<0><<<g, b3>>>(dX,  dWq, nullptr, nullptr);
    gemm3_k<1><<<g, b3>>>(dCT, dWk, nullptr, nullptr);
    gemm3_k<2><<<g, b3>>>(dCT, dWv, nullptr, nullptr);
    flash_k<<<dim3(8, 256, 1), dim3(128)>>>();
    gemm3_k<5><<<g, b3>>>(nullptr, dWo, out, bo);
}

// round 6
// speedup vs baseline: 1.0821x; 1.0821x over previous
#include <cuda_runtime.h>
#include <cstdint>

// Problem constants
#define DIMM  1024
#define HEADS 16
#define HDIM  64
#define BATCH 16
#define SEQ   512

// ---------------- scratch (device globals; no cudaMalloc allowed) ----------
__device__ float g_Q[(size_t)BATCH*HEADS*SEQ*HDIM];   // [b,h,s,d] tf32-rounded
__device__ float g_K[(size_t)BATCH*HEADS*SEQ*HDIM];
__device__ float g_V[(size_t)BATCH*HEADS*SEQ*HDIM];
__device__ float g_O[(size_t)BATCH*SEQ*DIMM];         // tf32-rounded
__device__ float g_X [(size_t)BATCH*SEQ*DIMM];        // x   tf32-rounded
__device__ float g_CT[(size_t)BATCH*SEQ*DIMM];        // ctx tf32-rounded
__device__ float g_Wq[DIMM*DIMM];
__device__ float g_Wk[DIMM*DIMM];
__device__ float g_Wv[DIMM*DIMM];
__device__ float g_Wo[DIMM*DIMM];

// ---------------- helpers ---------------------------------------------------
__device__ __forceinline__ float to_tf32(float x) {
    uint32_t u;
    asm("cvt.rna.tf32.f32 %0, %1;" : "=r"(u) : "f"(x));
    return __uint_as_float(u);
}

__device__ __forceinline__ void mma8(float* c,
                                     uint32_t a0, uint32_t a1, uint32_t a2, uint32_t a3,
                                     uint32_t b0, uint32_t b1) {
    asm volatile(
        "mma.sync.aligned.m16n8k8.row.col.f32.tf32.tf32.f32 "
        "{%0,%1,%2,%3},{%4,%5,%6,%7},{%8,%9},{%0,%1,%2,%3};"
        : "+f"(c[0]), "+f"(c[1]), "+f"(c[2]), "+f"(c[3])
        : "r"(a0), "r"(a1), "r"(a2), "r"(a3), "r"(b0), "r"(b1));
}

__device__ __forceinline__ void cp_async16(uint32_t s, const void* g) {
    asm volatile("cp.async.cg.shared.global [%0], [%1], 16;" :: "r"(s), "l"(g));
}
__device__ __forceinline__ void cp_commit() {
    asm volatile("cp.async.commit_group;");
}

// RoPE (tiled tables, adjacent-pair rotation), applied to fp32 accumulators.
__device__ __forceinline__ void rope_pair(float& e, float& o, int t, int d /*even*/) {
    const float LOG2_10000_OVER_32 = 0.41524101186092028f;
    int   i0  = d & 31;
    float fr0 = exp2f(-(float)i0       * LOG2_10000_OVER_32);
    float fr1 = exp2f(-(float)(i0 + 1) * LOG2_10000_OVER_32);
    float tf  = (float)t;
    float s0, c0, s1, c1;
    sincosf(tf * fr0, &s0, &c0);
    sincosf(tf * fr1, &s1, &c1);
    float ne = e * c0 - o * s0;
    float no = o * c1 + e * s1;
    e = ne; o = no;
}

// ---------------- tf32 pre-truncation pass -----------------------------------
__global__ void __launch_bounds__(256) trunc_k(const float* __restrict__ s,
                                               float* __restrict__ d, int n4) {
    int i = blockIdx.x * 256 + threadIdx.x;
    if (i < n4) {
        float4 v = reinterpret_cast<const float4*>(s)[i];
        v.x = to_tf32(v.x); v.y = to_tf32(v.y);
        v.z = to_tf32(v.z); v.w = to_tf32(v.w);
        reinterpret_cast<float4*>(d)[i] = v;
    }
}

// ---------------- 4-stage pipelined GEMM -------------------------------------
// CTA 128x128, BK=16, 256 threads (2x4 warps, 64x32 per warp), cp.async
// 4-stage pipeline, operands pre-truncated (no cvt in inner loop).
// MODE: 0 = Q proj (+RoPE), 1 = K proj (+RoPE), 2 = V proj, 5 = out = O@Wo+bo
#define AS_STRIDE 20
#define BS_STRIDE 136
#define AS_FLOATS (128 * AS_STRIDE)   // 2560
#define BS_FLOATS (16 * BS_STRIDE)    // 2176
#define GSTAGES 4
#define GEMM_SMEM ((GSTAGES * (AS_FLOATS + BS_FLOATS)) * 4)   // 75776 B

template <int MODE>
__global__ void __launch_bounds__(256) gemm4_k(const float* __restrict__ Ain,
                                               const float* __restrict__ Bin,
                                               float*       __restrict__ Cout,
                                               const float* __restrict__ bias) {
    extern __shared__ float sm[];
    float* AsBase = sm;                           // GSTAGES * 2560
    float* BsBase = sm + GSTAGES * AS_FLOATS;     // GSTAGES * 2176

    const int tid  = threadIdx.x;
    const int lane = tid & 31;
    const int warp = tid >> 5;
    const int wm   = warp >> 2;         // 0..1  (64 rows each)
    const int wn   = warp & 3;          // 0..3  (32 cols each)
    const int mBase = blockIdx.y * 128;
    const int nBase = blockIdx.x * 128;

    const float* A = (MODE == 5) ? g_O : Ain;
    const float* B = Bin;

    auto load_tiles = [&](int kt, int stage) {
        const int k0 = kt * 16;
        float* As = AsBase + stage * AS_FLOATS;
        float* Bs = BsBase + stage * BS_FLOATS;
        #pragma unroll
        for (int j = 0; j < 2; j++) {
            int idx = tid + j * 256;
            int r = idx >> 2, c4 = (idx & 3) * 4;
            cp_async16((uint32_t)__cvta_generic_to_shared(&As[r * AS_STRIDE + c4]),
                       A + (size_t)(mBase + r) * 1024 + k0 + c4);
        }
        #pragma unroll
        for (int j = 0; j < 2; j++) {
            int idx = tid + j * 256;
            int r = idx >> 5, c4 = (idx & 31) * 4;
            cp_async16((uint32_t)__cvta_generic_to_shared(&Bs[r * BS_STRIDE + c4]),
                       B + (size_t)(k0 + r) * 1024 + nBase + c4);
        }
        cp_commit();
    };

    float acc[4][4][4];
    #pragma unroll
    for (int i = 0; i < 4; i++)
        #pragma unroll
        for (int j = 0; j < 4; j++)
            #pragma unroll
            for (int k = 0; k < 4; k++) acc[i][j][k] = 0.f;

    // prologue: stages 0..2 in flight
    load_tiles(0, 0);
    load_tiles(1, 1);
    load_tiles(2, 2);

    const int NK = 64;
    for (int kt = 0; kt < NK; kt++) {
        const int stage = kt & (GSTAGES - 1);
        asm volatile("cp.async.wait_group 2;");   // stage kt complete
        __syncthreads();                          // visible to all; prev compute done
        if (kt + 3 < NK) load_tiles(kt + 3, (kt + 3) & (GSTAGES - 1));

        const float* Ab = AsBase + stage * AS_FLOATS;
        const float* Bb = BsBase + stage * BS_FLOATS;
        #pragma unroll
        for (int kk = 0; kk < 16; kk += 8) {
            const int cc = kk + (lane & 3);
            uint32_t af[4][4];
            #pragma unroll
            for (int mt = 0; mt < 4; mt++) {
                int r0 = (wm * 64 + mt * 16 + (lane >> 2)) * AS_STRIDE;
                af[mt][0] = __float_as_uint(Ab[r0 + cc]);
                af[mt][1] = __float_as_uint(Ab[r0 + 8 * AS_STRIDE + cc]);
                af[mt][2] = __float_as_uint(Ab[r0 + cc + 4]);
                af[mt][3] = __float_as_uint(Ab[r0 + 8 * AS_STRIDE + cc + 4]);
            }
            uint32_t bf[4][2];
            #pragma unroll
            for (int nt = 0; nt < 4; nt++) {
                int nb = wn * 32 + nt * 8 + (lane >> 2);
                bf[nt][0] = __float_as_uint(Bb[cc * BS_STRIDE + nb]);
                bf[nt][1] = __float_as_uint(Bb[(cc + 4) * BS_STRIDE + nb]);
            }
            #pragma unroll
            for (int mt = 0; mt < 4; mt++)
                #pragma unroll
                for (int nt = 0; nt < 4; nt++)
                    mma8(acc[mt][nt], af[mt][0], af[mt][1], af[mt][2], af[mt][3],
                         bf[nt][0], bf[nt][1]);
        }
        __syncthreads();   // all reads of this stage done before it is refilled
    }

    // --- epilogue ---
    #pragma unroll
    for (int mt = 0; mt < 4; mt++) {
        #pragma unroll
        for (int nt = 0; nt < 4; nt++) {
            int row = mBase + wm * 64 + mt * 16 + (lane >> 2);
            int col = nBase + wn * 32 + nt * 8 + 2 * (lane & 3);
            #pragma unroll
            for (int half = 0; half < 2; half++) {
                int   rr = row + half * 8;
                float e  = acc[mt][nt][half * 2 + 0];
                float o  = acc[mt][nt][half * 2 + 1];
                if constexpr (MODE <= 1) rope_pair(e, o, rr & (SEQ - 1), col & (HDIM - 1));
                if constexpr (MODE <= 2) {
                    int b = rr >> 9, s = rr & (SEQ - 1);
                    int h = col >> 6, d = col & (HDIM - 1);
                    float* out = (MODE == 0) ? g_Q : ((MODE == 1) ? g_K : g_V);
                    size_t off = (((size_t)(b * HEADS + h)) * SEQ + s) * HDIM + d;
                    *reinterpret_cast<float2*>(out + off) =
                        make_float2(to_tf32(e), to_tf32(o));   // pre-truncate for flash
                } else {
                    size_t off = (size_t)rr * DIMM + col;
                    *reinterpret_cast<float2*>(Cout + off) =
                        make_float2(e + bias[col], o + bias[col + 1]);
                }
            }
        }
    }
}

// ---------------- fused flash attention (double-buffered K/V) ---------------
// One CTA per (z = b*H+h, 64-row q tile). 4 warps, each owns 16 q rows.
// K/V tiles double-buffered via cp.async; dedicated P buffer (no extra sync).
#define KV_FLOATS (64 * 68)            // 4352 per tile buffer
#define FLASH_SMEM ((5 * KV_FLOATS) * 4)   // 2xK + 2xV + P = 87040 B

__global__ void __launch_bounds__(128) flash_k() {
    extern __shared__ float sm[];
    float* Ks = sm;                    // 2 stages
    float* Vs = sm + 2 * KV_FLOATS;    // 2 stages
    float* Ps = sm + 4 * KV_FLOATS;    // 64x68

    const int z     = blockIdx.y;
    const int qBase = blockIdx.x * 64;
    const int lane  = threadIdx.x & 31;
    const int warp  = threadIdx.x >> 5;

    const float* Qp = g_Q + (size_t)z * SEQ * HDIM;
    const float* Kp = g_K + (size_t)z * SEQ * HDIM;
    const float* Vp = g_V + (size_t)z * SEQ * HDIM;

    auto load_kv = [&](int kt, int stage) {
        const float* Kt = Kp + (size_t)kt * 64 * HDIM;
        const float* Vt = Vp + (size_t)kt * 64 * HDIM;
        float* kd = Ks + stage * KV_FLOATS;
        float* vd = Vs + stage * KV_FLOATS;
        #pragma unroll
        for (int i = 0; i < 8; i++) {
            int idx = threadIdx.x + i * 128;
            int rr = idx >> 4, cc = (idx & 15) * 4;
            cp_async16((uint32_t)__cvta_generic_to_shared(&kd[rr * 68 + cc]),
                       Kt + rr * HDIM + cc);
            cp_async16((uint32_t)__cvta_generic_to_shared(&vd[rr * 68 + cc]),
                       Vt + rr * HDIM + cc);
        }
        cp_commit();
    };

    // Q fragments with scale folded in (x0.125 = exponent shift, exact)
    uint32_t qa[8][4];
    {
        const int r0 = qBase + warp * 16 + (lane >> 2);
        #pragma unroll
        for (int kk = 0; kk < 8; kk++) {
            int c = kk * 8 + (lane & 3);
            qa[kk][0] = __float_as_uint(Qp[(size_t)r0       * HDIM + c]     * 0.125f);
            qa[kk][1] = __float_as_uint(Qp[(size_t)(r0 + 8) * HDIM + c]     * 0.125f);
            qa[kk][2] = __float_as_uint(Qp[(size_t)r0       * HDIM + c + 4] * 0.125f);
            qa[kk][3] = __float_as_uint(Qp[(size_t)(r0 + 8) * HDIM + c + 4] * 0.125f);
        }
    }

    float m0 = -1e30f, m1 = -1e30f, l0 = 0.f, l1 = 0.f;
    float o[8][4];
    #pragma unroll
    for (int nt = 0; nt < 8; nt++)
        #pragma unroll
        for (int i = 0; i < 4; i++) o[nt][i] = 0.f;

    load_kv(0, 0);

    for (int kt = 0; kt < 8; kt++) {
        const int stage = kt & 1;
        __syncthreads();                  // everyone done with buffer (kt+1)&1 from iter kt-1
        if (kt + 1 < 8) {
            load_kv(kt + 1, stage ^ 1);
            asm volatile("cp.async.wait_group 1;");   // stage kt complete
        } else {
            asm volatile("cp.async.wait_group 0;");
        }
        __syncthreads();                  // stage kt visible to all warps

        const float* Kb = Ks + stage * KV_FLOATS;
        const float* Vb = Vs + stage * KV_FLOATS;

        // ---- S = (Q*scale) K^T (16x64 per warp) ----
        float s[8][4];
        #pragma unroll
        for (int nt = 0; nt < 8; nt++)
            #pragma unroll
            for (int i = 0; i < 4; i++) s[nt][i] = 0.f;
        #pragma unroll
        for (int kk = 0; kk < 8; kk++) {
            const int d0 = kk * 8 + (lane & 3);
            #pragma unroll
            for (int nt = 0; nt < 8; nt++) {
                const int kvr = nt * 8 + (lane >> 2);
                uint32_t b0 = __float_as_uint(Kb[kvr * 68 + d0]);
                uint32_t b1 = __float_as_uint(Kb[kvr * 68 + d0 + 4]);
                mma8(s[nt], qa[kk][0], qa[kk][1], qa[kk][2], qa[kk][3], b0, b1);
            }
        }

        // ---- online softmax ----
        float mr0 = -1e30f, mr1 = -1e30f;
        #pragma unroll
        for (int nt = 0; nt < 8; nt++) {
            mr0 = fmaxf(mr0, fmaxf(s[nt][0], s[nt][1]));
            mr1 = fmaxf(mr1, fmaxf(s[nt][2], s[nt][3]));
        }
        mr0 = fmaxf(mr0, __shfl_xor_sync(0xffffffffu, mr0, 1));
        mr0 = fmaxf(mr0, __shfl_xor_sync(0xffffffffu, mr0, 2));
        mr1 = fmaxf(mr1, __shfl_xor_sync(0xffffffffu, mr1, 1));
        mr1 = fmaxf(mr1, __shfl_xor_sync(0xffffffffu, mr1, 2));

        float nm0 = fmaxf(m0, mr0), nm1 = fmaxf(m1, mr1);
        float f0 = __expf(m0 - nm0), f1 = __expf(m1 - nm1);
        m0 = nm0; m1 = nm1;

        float sum0 = 0.f, sum1 = 0.f;
        #pragma unroll
        for (int nt = 0; nt < 8; nt++) {
            s[nt][0] = __expf(s[nt][0] - m0);
            s[nt][1] = __expf(s[nt][1] - m0);
            s[nt][2] = __expf(s[nt][2] - m1);
            s[nt][3] = __expf(s[nt][3] - m1);
            sum0 += s[nt][0] + s[nt][1];
            sum1 += s[nt][2] + s[nt][3];
        }
        sum0 += __shfl_xor_sync(0xffffffffu, sum0, 1);
        sum0 += __shfl_xor_sync(0xffffffffu, sum0, 2);
        sum1 += __shfl_xor_sync(0xffffffffu, sum1, 1);
        sum1 += __shfl_xor_sync(0xffffffffu, sum1, 2);
        l0 = l0 * f0 + sum0;
        l1 = l1 * f1 + sum1;

        #pragma unroll
        for (int nt = 0; nt < 8; nt++) {
            o[nt][0] *= f0; o[nt][1] *= f0;
            o[nt][2] *= f1; o[nt][3] *= f1;
        }

        // ---- P -> dedicated smem buffer (warp-private rows) ----
        {
            const int pr = warp * 16 + (lane >> 2);
            #pragma unroll
            for (int nt = 0; nt < 8; nt++) {
                int c = nt * 8 + 2 * (lane & 3);
                Ps[pr * 68 + c]           = to_tf32(s[nt][0]);
                Ps[pr * 68 + c + 1]       = to_tf32(s[nt][1]);
                Ps[(pr + 8) * 68 + c]     = to_tf32(s[nt][2]);
                Ps[(pr + 8) * 68 + c + 1] = to_tf32(s[nt][3]);
            }
        }
        __syncwarp();

        // ---- O += P V ----
        #pragma unroll
        for (int kk = 0; kk < 8; kk++) {
            const int pq = warp * 16 + (lane >> 2);
            const int kv = kk * 8 + (lane & 3);
            uint32_t pa0 = __float_as_uint(Ps[pq * 68 + kv]);
            uint32_t pa1 = __float_as_uint(Ps[(pq + 8) * 68 + kv]);
            uint32_t pa2 = __float_as_uint(Ps[pq * 68 + kv + 4]);
            uint32_t pa3 = __float_as_uint(Ps[(pq + 8) * 68 + kv + 4]);
            #pragma unroll
            for (int nt = 0; nt < 8; nt++) {
                const int dc = nt * 8 + (lane >> 2);
                uint32_t b0 = __float_as_uint(Vb[kv * 68 + dc]);
                uint32_t b1 = __float_as_uint(Vb[(kv + 4) * 68 + dc]);
                mma8(o[nt], pa0, pa1, pa2, pa3, b0, b1);
            }
        }
    }

    // ---- epilogue: O /= l, tf32-truncate (consumed by gemm4<5>), write ----
    const float inv0 = 1.f / l0, inv1 = 1.f / l1;
    const int b = z >> 4, h = z & 15;
    const int row = qBase + warp * 16 + (lane >> 2);
    #pragma unroll
    for (int nt = 0; nt < 8; nt++) {
        int col = h * HDIM + nt * 8 + 2 * (lane & 3);
        *reinterpret_cast<float2*>(g_O + (size_t)(b * SEQ + row) * DIMM + col)
            = make_float2(to_tf32(o[nt][0] * inv0), to_tf32(o[nt][1] * inv0));
        *reinterpret_cast<float2*>(g_O + (size_t)(b * SEQ + row + 8) * DIMM + col)
            = make_float2(to_tf32(o[nt][2] * inv1), to_tf32(o[nt][3] * inv1));
    }
}

// ---------------- launch -----------------------------------------------------
extern "C" void kernel_launch(void* const* d_in, const int* in_sizes, int n_in,
                              void* d_out, int out_size) {
    (void)in_sizes; (void)n_in; (void)out_size;
    const float* x   = (const float*)d_in[0];
    const float* ctx = (const float*)d_in[1];
    const float* Wq  = (const float*)d_in[2];
    const float* Wk  = (const float*)d_in[3];
    const float* Wv  = (const float*)d_in[4];
    const float* Wo  = (const float*)d_in[5];
    const float* bo  = (const float*)d_in[6];
    float* out = (float*)d_out;

    static bool attr_done = false;
    if (!attr_done) {
        cudaFuncSetAttribute(gemm4_k<0>, cudaFuncAttributeMaxDynamicSharedMemorySize, GEMM_SMEM);
        cudaFuncSetAttribute(gemm4_k<1>, cudaFuncAttributeMaxDynamicSharedMemorySize, GEMM_SMEM);
        cudaFuncSetAttribute(gemm4_k<2>, cudaFuncAttributeMaxDynamicSharedMemorySize, GEMM_SMEM);
        cudaFuncSetAttribute(gemm4_k<5>, cudaFuncAttributeMaxDynamicSharedMemorySize, GEMM_SMEM);
        cudaFuncSetAttribute(flash_k,    cudaFuncAttributeMaxDynamicSharedMemorySize, FLASH_SMEM);
        attr_done = true;
    }

    float *dX, *dCT, *dWq, *dWk, *dWv, *dWo;
    cudaGetSymbolAddress((void**)&dX,  g_X);
    cudaGetSymbolAddress((void**)&dCT, g_CT);
    cudaGetSymbolAddress((void**)&dWq, g_Wq);
    cudaGetSymbolAddress((void**)&dWk, g_Wk);
    cudaGetSymbolAddress((void**)&dWv, g_Wv);
    cudaGetSymbolAddress((void**)&dWo, g_Wo);

    const int nBig = BATCH * SEQ * DIMM / 4;   // 2M float4
    const int nW   = DIMM * DIMM / 4;          // 256K float4
    trunc_k<<<(nBig + 255) / 256, 256>>>(x,   dX,  nBig);
    trunc_k<<<(nBig + 255) / 256, 256>>>(ctx, dCT, nBig);
    trunc_k<<<(nW   + 255) / 256, 256>>>(Wq,  dWq, nW);
    trunc_k<<<(nW   + 255) / 256, 256>>>(Wk,  dWk, nW);
    trunc_k<<<(nW   + 255) / 256, 256>>>(Wv,  dWv, nW);
    trunc_k<<<(nW   + 255) / 256, 256>>>(Wo,  dWo, nW);

    dim3 g(8, 64), b2(256);
    gemm4_k<0><<<g, b2, GEMM_SMEM>>>(dX,  dWq, nullptr, nullptr);
    gemm4_k<1><<<g, b2, GEMM_SMEM>>>(dCT, dWk, nullptr, nullptr);
    gemm4_k<2><<<g, b2, GEMM_SMEM>>>(dCT, dWv, nullptr, nullptr);
    flash_k<<<dim3(8, 256, 1), dim3(128), FLASH_SMEM>>>();
    gemm4_k<5><<<g, b2, GEMM_SMEM>>>(nullptr, dWo, out, bo);
}